// round 1
// baseline (speedup 1.0000x reference)
#include <cuda_runtime.h>
#include <cuda_bf16.h>

// QuantumSubgenerator: 12-qubit RY/CNOT-ring/RY circuit + <Z_q> readout,
// reduced exactly via the Heisenberg picture to closed-form trig products.
//
//   alpha_q = latent[b][q] + w0[q]   (first two RY layers fuse: RY(a)RY(b)=RY(a+b))
//   c_q = cos(alpha_q), s_q = sin(alpha_q), theta_q = w1[q]
//   out[b][0]  = cos(th_0) * prod_{r=1..11} c_r   - sin(th_0) * s_0*s_1
//   out[b][q]  = cos(th_q) * prod_{r=0..q}  c_r   - sin(th_q) * s_q*s_{q+1}   (1<=q<=10)
//   out[b][11] = cos(th_11)* prod_{r=0..11} c_r   - sin(th_11)* s_0*s_1*s_11
//
// Derivation: |psi> = R C |prod>, out_q = <prod| C^T R^T Z_q R C |prod>;
// RY^T Z RY = cos(th) Z - sin(th) X; CNOT conjugation: Z_t -> Z_c Z_t,
// X_c -> X_c X_t; product-state expectations factor (<Z_r>=cos a_r, <X_r>=sin a_r).

#define NQ 12

__global__ void __launch_bounds__(128)
QuantumSubgenerator_25314537242888_kernel(const float* __restrict__ latent,
                                          const float* __restrict__ weights,
                                          float* __restrict__ out, int B) {
    int b = blockIdx.x * blockDim.x + threadIdx.x;
    if (b >= B) return;

    // Vector-load this batch element's 12 latent angles (48B, 16B-aligned).
    const float4* lat4 = reinterpret_cast<const float4*>(latent + (size_t)b * NQ);
    float4 l0 = lat4[0], l1 = lat4[1], l2 = lat4[2];
    float lv[NQ] = {l0.x, l0.y, l0.z, l0.w,
                    l1.x, l1.y, l1.z, l1.w,
                    l2.x, l2.y, l2.z, l2.w};

    float c[NQ], s[NQ];
#pragma unroll
    for (int q = 0; q < NQ; q++) {
        float a = lv[q] + __ldg(&weights[q]);      // alpha_q = latent + w0
        sincosf(a, &s[q], &c[q]);
    }

    float cw[NQ], sw[NQ];
#pragma unroll
    for (int q = 0; q < NQ; q++) {
        sincosf(__ldg(&weights[NQ + q]), &sw[q], &cw[q]);  // theta_q = w1
    }

    float o[NQ];

    // out[0]: Z-string {1..11}, X-string {0,1}
    float p1to11 = 1.0f;
#pragma unroll
    for (int q = 1; q < NQ; q++) p1to11 *= c[q];
    o[0] = cw[0] * p1to11 - sw[0] * (s[0] * s[1]);

    // out[q] for q=1..10: Z-string {0..q}, X-string {q,q+1}
    float pref = c[0];
#pragma unroll
    for (int q = 1; q < NQ - 1; q++) {
        pref *= c[q];
        o[q] = cw[q] * pref - sw[q] * (s[q] * s[q + 1]);
    }

    // out[11]: Z-string {0..11}, X-string {0,1,11}
    pref *= c[NQ - 1];
    o[NQ - 1] = cw[NQ - 1] * pref - sw[NQ - 1] * (s[0] * s[1] * s[NQ - 1]);

    float4* out4 = reinterpret_cast<float4*>(out + (size_t)b * NQ);
    out4[0] = make_float4(o[0], o[1], o[2],  o[3]);
    out4[1] = make_float4(o[4], o[5], o[6],  o[7]);
    out4[2] = make_float4(o[8], o[9], o[10], o[11]);
}

extern "C" void kernel_launch(void* const* d_in, const int* in_sizes, int n_in,
                              void* d_out, int out_size) {
    const float* latent  = (const float*)d_in[0];
    const float* weights = (const float*)d_in[1];
    int lat_sz = in_sizes[0];
    // Robust to input-order surprises: weights tensor has exactly 2*NQ elems.
    if (n_in >= 2 && in_sizes[0] == 2 * NQ) {
        latent  = (const float*)d_in[1];
        weights = (const float*)d_in[0];
        lat_sz  = in_sizes[1];
    }
    int B = lat_sz / NQ;
    int threads = 128;
    int blocks  = (B + threads - 1) / threads;
    QuantumSubgenerator_25314537242888_kernel<<<blocks, threads>>>(
        latent, weights, (float*)d_out, B);
}